// round 8
// baseline (speedup 1.0000x reference)
#include <cuda_runtime.h>
#include <math.h>
#include <stdint.h>

#define BZ   128
#define T    32
#define D    768
#define DFF  3072
#define NE   8
#define NROWS 256
#define OUT_ELEMS (NROWS*T*D)
#define MAX_TILES 72

#define NT        128                 // CTA N tile
#define KC        32                  // K chunk
#define STAGES    3
#define AS_STRIDE 36                  // floats per A smem row
#define BS_STRIDE 136                 // floats per B smem k-row
#define A_STAGE   (128*AS_STRIDE)     // 4608 floats
#define B_STAGE   (KC*BS_STRIDE)      // 4352 floats
#define STAGE_FLOATS (A_STAGE + B_STAGE)       // 8960
#define SMEM_BYTES   (STAGES*STAGE_FLOATS*4)   // 107520

// ---------------- scratch ---------------------------------------------------
__device__ float g_xavg[BZ*D];
__device__ int   g_sel[NROWS];
__device__ int   g_perm[NROWS];
__device__ int   g_tile_e[MAX_TILES];
__device__ int   g_tile_p0[MAX_TILES];
__device__ int   g_tile_rows[MAX_TILES];
__device__ int   g_ntiles;
__device__ float g_xr[(size_t)BZ*T*D];       // tf32-rounded copy of x
__device__ float g_h[(size_t)NROWS*T*DFF];   // intermediate (tf32-rounded), grouped

__device__ __forceinline__ float gelu_exact(float v) {
    return 0.5f * v * (1.0f + erff(v * 0.70710678118654752f));
}
__device__ __forceinline__ uint32_t cvt_tf32(float f) {
    uint32_t u;
    asm("cvt.rna.tf32.f32 %0, %1;" : "=r"(u) : "f"(f));
    return u;
}
__device__ __forceinline__ void mma_tf32(float* c,
                                         uint32_t a0, uint32_t a1, uint32_t a2, uint32_t a3,
                                         uint32_t b0, uint32_t b1) {
    asm volatile(
        "mma.sync.aligned.m16n8k8.row.col.f32.tf32.tf32.f32 "
        "{%0,%1,%2,%3}, {%4,%5,%6,%7}, {%8,%9}, {%0,%1,%2,%3};"
        : "+f"(c[0]), "+f"(c[1]), "+f"(c[2]), "+f"(c[3])
        : "r"(a0), "r"(a1), "r"(a2), "r"(a3), "r"(b0), "r"(b1));
}
__device__ __forceinline__ void cp16(uint32_t saddr, const void* g) {
    asm volatile("cp.async.cg.shared.global [%0], [%1], 16;" :: "r"(saddr), "l"(g));
}

// ---------------- kernel 0: tf32-round x ------------------------------------
__global__ void round_x_kernel(const float* __restrict__ x) {
    int i = blockIdx.x * blockDim.x + threadIdx.x;
    const int n4 = BZ*T*D/4;
    if (i < n4) {
        float4 v = ((const float4*)x)[i];
        uint4 r = make_uint4(cvt_tf32(v.x), cvt_tf32(v.y), cvt_tf32(v.z), cvt_tf32(v.w));
        ((uint4*)g_xr)[i] = r;
    }
}

// ---------------- kernel 1: x_avg (raw x, full precision) -------------------
__global__ void avg_kernel(const float* __restrict__ x) {
    int b = blockIdx.x;
    for (int d = threadIdx.x; d < D; d += blockDim.x) {
        float s = 0.f;
        #pragma unroll
        for (int t = 0; t < T; t++) s += x[((size_t)b*T + t)*D + d];
        g_xavg[b*D + d] = s * (1.0f / T);
    }
}

// ---------------- kernel 2: router ------------------------------------------
__global__ void router_kernel(const float* __restrict__ Wg,
                              float* __restrict__ dout, int out_size) {
    int b = blockIdx.x;
    int lane = threadIdx.x;
    int e = lane & 7;
    int chunk = lane >> 3;
    float part = 0.f;
    const float* xa = g_xavg + b*D;
    for (int d = chunk*192; d < (chunk+1)*192; d++) part += xa[d] * Wg[d*NE + e];
    part += __shfl_down_sync(0xffffffffu, part, 16);
    part += __shfl_down_sync(0xffffffffu, part, 8);
    float lv[NE];
    #pragma unroll
    for (int i = 0; i < NE; i++) lv[i] = __shfl_sync(0xffffffffu, part, i);

    if (lane == 0) {
        float mx = lv[0];
        #pragma unroll
        for (int i = 1; i < NE; i++) mx = fmaxf(mx, lv[i]);
        float p[NE]; float sum = 0.f;
        #pragma unroll
        for (int i = 0; i < NE; i++) { p[i] = __expf(lv[i] - mx); sum += p[i]; }
        float inv = 1.0f / sum;
        #pragma unroll
        for (int i = 0; i < NE; i++) p[i] *= inv;
        int i0 = 0;
        #pragma unroll
        for (int i = 1; i < NE; i++) if (p[i] > p[i0]) i0 = i;
        int i1 = (i0 == 0) ? 1 : 0;
        #pragma unroll
        for (int i = 0; i < NE; i++) if (i != i0 && p[i] > p[i1]) i1 = i;
        g_sel[2*b] = i0; g_sel[2*b+1] = i1;
        if (out_size >= OUT_ELEMS + 2*NROWS) {
            dout[OUT_ELEMS + 2*b]             = p[i0];
            dout[OUT_ELEMS + 2*b + 1]         = p[i1];
            dout[OUT_ELEMS + NROWS + 2*b]     = (float)i0;
            dout[OUT_ELEMS + NROWS + 2*b + 1] = (float)i1;
        }
    }
}

// ---------------- kernel 3: group rows by expert (parallel, smem) -----------
__global__ void group_kernel() {
    __shared__ int ssel[NROWS];
    __shared__ int shist[NE];
    __shared__ int soff[NE];
    int t = threadIdx.x;
    if (t < NE) shist[t] = 0;
    __syncthreads();
    ssel[t] = g_sel[t];
    __syncthreads();
    atomicAdd(&shist[ssel[t]], 1);
    __syncthreads();
    if (t == 0) {
        int pos = 0, tiles = 0;
        for (int e = 0; e < NE; e++) {
            soff[e] = pos;
            int cnt = shist[e];
            for (int r = 0; r < cnt; r += 4) {
                g_tile_e[tiles] = e; g_tile_p0[tiles] = pos + r;
                g_tile_rows[tiles] = min(4, cnt - r); tiles++;
            }
            pos += cnt;
        }
        g_ntiles = tiles;
    }
    __syncthreads();
    // stable rank: #earlier rows with same expert
    int mysel = ssel[t], rank = 0;
    for (int m = 0; m < NROWS; m++)
        if (m < t && ssel[m] == mysel) rank++;
    g_perm[soff[mysel] + rank] = t;
}

// ---------------- tf32 mma.sync GEMM, cp.async 3-stage, 2 CTA/SM ------------
// PHASE 1: g_h = round(gelu(Xr_perm @ W1[e] + b1[e]));  K=768,  N=3072
// PHASE 2 (split-K=2): out[perm] += g_h @ W2[e](+b2 on kp0); K=1536/part
// CTA 128x128, 256 threads / 8 warps (2m x 4n), warp tile 64x32.
template<int PHASE>
__global__ __launch_bounds__(256, 2) void ffn_mma(
    const float* __restrict__ X,
    const float* __restrict__ W1, const float* __restrict__ b1,
    const float* __restrict__ W2, const float* __restrict__ b2,
    float* __restrict__ out)
{
    const int mt = blockIdx.x;
    if (mt >= g_ntiles) return;
    const int e     = g_tile_e[mt];
    const int p0    = g_tile_p0[mt];
    const int nrows = g_tile_rows[mt];
    const int kp    = (PHASE == 2) ? blockIdx.z : 0;
    const int NF    = (PHASE == 1) ? DFF : D;
    const int kbase = (PHASE == 2) ? kp * (DFF/2) : 0;
    const int NC    = ((PHASE == 1) ? D : DFF/2) / KC;
    const float* __restrict__ Bsrc = (PHASE == 1) ? (W1 + (size_t)e*D*DFF)
                                                  : (W2 + (size_t)e*DFF*D);
    const int n0 = blockIdx.y * NT;
    const int tid = threadIdx.x, wid = tid >> 5, lane = tid & 31;

    extern __shared__ float smf[];

    // ---- async loader assignment (256 threads) ----
    // A: 128 rows x 32 floats (8x16B); thread -> row tid>>1, segs (tid&1)*4+i
    // B: 32 k-rows x 128 floats (32x16B); thread -> row tid>>3, segs (tid&7)+8i
    const int arow = tid >> 1, aseg4 = (tid & 1) * 4;
    const int brow = tid >> 3, bseg = tid & 7;

    const float* aglob;
    {
        int r = ((arow >> 5) < nrows) ? arow : (arow & 31);  // clamp pad rows
        if (PHASE == 1) {
            int n = g_perm[p0 + (r >> 5)];
            aglob = g_xr + ((size_t)(n >> 1)*T + (r & 31)) * (size_t)D;
        } else {
            aglob = g_h + ((size_t)(p0*T + r)) * (size_t)DFF;
        }
    }
    const float* bglob = Bsrc + (size_t)brow*NF + n0;

    uint32_t sbase = (uint32_t)__cvta_generic_to_shared(smf);
    uint32_t aSts[STAGES], bSts[STAGES];
    #pragma unroll
    for (int s = 0; s < STAGES; s++) {
        aSts[s] = sbase + (s*STAGE_FLOATS + arow*AS_STRIDE)*4;
        bSts[s] = sbase + (s*STAGE_FLOATS + A_STAGE + brow*BS_STRIDE)*4;
    }

    #define ISSUE(k0, s) do {                                                 \
        _Pragma("unroll")                                                     \
        for (int i = 0; i < 4; i++)                                           \
            cp16(aSts[s] + (aseg4 + i)*16, aglob + (k0) + (aseg4 + i)*4);     \
        _Pragma("unroll")                                                     \
        for (int i = 0; i < 4; i++)                                           \
            cp16(bSts[s] + (bseg + 8*i)*16,                                   \
                 bglob + (size_t)(k0)*NF + (bseg + 8*i)*4);                   \
    } while (0)

    // ---- mma fragment bases (per stage); warp tile 64x32 ----
    const int wm = (wid & 1) * 64;
    const int wn = (wid >> 1) * 32;
    const int g  = lane >> 2;
    const int t  = lane & 3;
    const float* Abf[STAGES];
    const float* Bbf[STAGES];
    #pragma unroll
    for (int s = 0; s < STAGES; s++) {
        Abf[s] = smf + s*STAGE_FLOATS + (wm + g)*AS_STRIDE + t;
        Bbf[s] = smf + s*STAGE_FLOATS + A_STAGE + t*BS_STRIDE + wn + g;
    }

    float acc[4][4][4];
    #pragma unroll
    for (int i = 0; i < 4; i++)
        #pragma unroll
        for (int j = 0; j < 4; j++)
            #pragma unroll
            for (int q = 0; q < 4; q++) acc[i][j][q] = 0.f;

    // A data pre-rounded (g_xr / g_h stored rounded): raw bit reuse.
    #define CONSUME(Ab, Bb) do {                                              \
        _Pragma("unroll")                                                     \
        for (int ks = 0; ks < 4; ks++) {                                      \
            uint32_t af[4][4], bf[4][2];                                      \
            _Pragma("unroll")                                                 \
            for (int mi = 0; mi < 4; mi++) {                                  \
                af[mi][0] = __float_as_uint((Ab)[mi*16*AS_STRIDE + ks*8]);    \
                af[mi][1] = __float_as_uint((Ab)[mi*16*AS_STRIDE + ks*8 + 8*AS_STRIDE]); \
                af[mi][2] = __float_as_uint((Ab)[mi*16*AS_STRIDE + ks*8 + 4]);\
                af[mi][3] = __float_as_uint((Ab)[mi*16*AS_STRIDE + ks*8 + 8*AS_STRIDE + 4]); \
            }                                                                 \
            _Pragma("unroll")                                                 \
            for (int ni = 0; ni < 4; ni++) {                                  \
                bf[ni][0] = cvt_tf32((Bb)[ks*8*BS_STRIDE + ni*8]);            \
                bf[ni][1] = cvt_tf32((Bb)[ks*8*BS_STRIDE + ni*8 + 4*BS_STRIDE]); \
            }                                                                 \
            _Pragma("unroll")                                                 \
            for (int mi = 0; mi < 4; mi++)                                    \
                _Pragma("unroll")                                             \
                for (int ni = 0; ni < 4; ni++)                                \
                    mma_tf32(acc[mi][ni], af[mi][0], af[mi][1], af[mi][2],    \
                             af[mi][3], bf[ni][0], bf[ni][1]);                \
        }                                                                     \
    } while (0)

    // ---- prologue: chunks 0,1 in flight ----
    ISSUE(kbase, 0);
    asm volatile("cp.async.commit_group;" ::: "memory");
    ISSUE(kbase + KC, 1);
    asm volatile("cp.async.commit_group;" ::: "memory");

    // ---- main loop: single barrier per chunk ----
    for (int c = 0; c < NC; c++) {
        asm volatile("cp.async.wait_group 1;" ::: "memory");
        __syncthreads();                 // chunk c visible; consume(c-1) done
        if (c + 2 < NC) ISSUE(kbase + (c + 2)*KC, (c + 2) % STAGES);
        asm volatile("cp.async.commit_group;" ::: "memory");
        switch (c % STAGES) {
            case 0: CONSUME(Abf[0], Bbf[0]); break;
            case 1: CONSUME(Abf[1], Bbf[1]); break;
            default: CONSUME(Abf[2], Bbf[2]); break;
        }
    }

    // ---- epilogue ----
    const float* bias = (PHASE == 1) ? (b1 + e*DFF + n0) : (b2 + e*D + n0);
    #pragma unroll
    for (int mi = 0; mi < 4; mi++) {
        #pragma unroll
        for (int h = 0; h < 2; h++) {
            int r = wm + 16*mi + g + 8*h;
            int br = r >> 5;
            if (br >= nrows) continue;
            if (PHASE == 1) {
                float* dst = g_h + ((size_t)(p0*T + r)) * (size_t)DFF + n0;
                #pragma unroll
                for (int ni = 0; ni < 4; ni++) {
                    int col = wn + 8*ni + 2*t;
                    float v0 = gelu_exact(acc[mi][ni][2*h + 0] + bias[col]);
                    float v1 = gelu_exact(acc[mi][ni][2*h + 1] + bias[col + 1]);
                    uint2 w = make_uint2(cvt_tf32(v0), cvt_tf32(v1));
                    *(uint2*)(dst + col) = w;
                }
            } else {
                int n = g_perm[p0 + br];
                float* dst = out + ((size_t)n*T + (r & 31)) * (size_t)D + n0;
                #pragma unroll
                for (int ni = 0; ni < 4; ni++) {
                    int col = wn + 8*ni + 2*t;
                    float v0 = acc[mi][ni][2*h + 0];
                    float v1 = acc[mi][ni][2*h + 1];
                    if (kp == 0) { v0 += bias[col]; v1 += bias[col + 1]; }
                    // exactly 2 atomic contributions per element onto 0-init:
                    // order-invariant -> deterministic
                    atomicAdd(dst + col,     v0);
                    atomicAdd(dst + col + 1, v1);
                }
            }
        }
    }
    #undef ISSUE
    #undef CONSUME
}

// ---------------- launch ----------------------------------------------------
extern "C" void kernel_launch(void* const* d_in, const int* in_sizes, int n_in,
                              void* d_out, int out_size) {
    const float* x  = (const float*)d_in[0];
    const float* Wg = (const float*)d_in[2];
    const float* W1 = (const float*)d_in[3];
    const float* b1 = (const float*)d_in[4];
    const float* W2 = (const float*)d_in[5];
    const float* b2 = (const float*)d_in[6];
    float* out = (float*)d_out;

    cudaFuncSetAttribute(ffn_mma<1>, cudaFuncAttributeMaxDynamicSharedMemorySize, SMEM_BYTES);
    cudaFuncSetAttribute(ffn_mma<2>, cudaFuncAttributeMaxDynamicSharedMemorySize, SMEM_BYTES);

    cudaMemsetAsync(out, 0, (size_t)OUT_ELEMS * sizeof(float));
    round_x_kernel<<<(BZ*T*D/4 + 255)/256, 256>>>(x);
    avg_kernel<<<BZ, 256>>>(x);
    router_kernel<<<BZ, 32>>>(Wg, out, out_size);
    group_kernel<<<1, NROWS>>>();
    ffn_mma<1><<<dim3(MAX_TILES, DFF/NT),  256, SMEM_BYTES>>>(x, W1, b1, W2, b2, out);
    ffn_mma<2><<<dim3(MAX_TILES, D/NT, 2), 256, SMEM_BYTES>>>(x, W1, b1, W2, b2, out);
}

// round 9
// speedup vs baseline: 1.0545x; 1.0545x over previous
#include <cuda_runtime.h>
#include <math.h>
#include <stdint.h>

#define BZ   128
#define T    32
#define D    768
#define DFF  3072
#define NE   8
#define NROWS 256
#define OUT_ELEMS (NROWS*T*D)
#define MAX_TILES 72

#define NT        256                 // CTA N tile
#define KC        64                  // K chunk
#define STAGES    2
#define AS_STRIDE 68                  // floats per A smem row (64+4 pad)
#define BS_STRIDE 264                 // floats per B smem k-row (256+8 pad)
#define A_STAGE   (128*AS_STRIDE)     // 8704 floats
#define B_STAGE   (KC*BS_STRIDE)      // 16896 floats
#define STAGE_FLOATS (A_STAGE + B_STAGE)       // 25600
#define SMEM_BYTES   (STAGES*STAGE_FLOATS*4)   // 204800

// ---------------- scratch ---------------------------------------------------
__device__ float g_xavg[BZ*D];
__device__ int   g_sel[NROWS];
__device__ int   g_perm[NROWS];
__device__ int   g_tile_e[MAX_TILES];
__device__ int   g_tile_p0[MAX_TILES];
__device__ int   g_tile_rows[MAX_TILES];
__device__ int   g_ntiles;
__device__ float g_xr[(size_t)BZ*T*D];       // tf32-rounded copy of x
__device__ float g_h[(size_t)NROWS*T*DFF];   // intermediate (tf32-rounded), grouped

__device__ __forceinline__ float gelu_exact(float v) {
    return 0.5f * v * (1.0f + erff(v * 0.70710678118654752f));
}
__device__ __forceinline__ uint32_t cvt_tf32(float f) {
    uint32_t u;
    asm("cvt.rna.tf32.f32 %0, %1;" : "=r"(u) : "f"(f));
    return u;
}
__device__ __forceinline__ void mma_tf32(float* c,
                                         uint32_t a0, uint32_t a1, uint32_t a2, uint32_t a3,
                                         uint32_t b0, uint32_t b1) {
    asm volatile(
        "mma.sync.aligned.m16n8k8.row.col.f32.tf32.tf32.f32 "
        "{%0,%1,%2,%3}, {%4,%5,%6,%7}, {%8,%9}, {%0,%1,%2,%3};"
        : "+f"(c[0]), "+f"(c[1]), "+f"(c[2]), "+f"(c[3])
        : "r"(a0), "r"(a1), "r"(a2), "r"(a3), "r"(b0), "r"(b1));
}
__device__ __forceinline__ void cp16(uint32_t saddr, const void* g) {
    asm volatile("cp.async.cg.shared.global [%0], [%1], 16;" :: "r"(saddr), "l"(g));
}

// ---------------- kernel 0: tf32-round x ------------------------------------
__global__ void round_x_kernel(const float* __restrict__ x) {
    int i = blockIdx.x * blockDim.x + threadIdx.x;
    const int n4 = BZ*T*D/4;
    if (i < n4) {
        float4 v = ((const float4*)x)[i];
        uint4 r = make_uint4(cvt_tf32(v.x), cvt_tf32(v.y), cvt_tf32(v.z), cvt_tf32(v.w));
        ((uint4*)g_xr)[i] = r;
    }
}

// ---------------- kernel 1: x_avg (raw x, full precision) -------------------
__global__ void avg_kernel(const float* __restrict__ x) {
    int b = blockIdx.x;
    for (int d = threadIdx.x; d < D; d += blockDim.x) {
        float s = 0.f;
        #pragma unroll
        for (int t = 0; t < T; t++) s += x[((size_t)b*T + t)*D + d];
        g_xavg[b*D + d] = s * (1.0f / T);
    }
}

// ---------------- kernel 2: router ------------------------------------------
__global__ void router_kernel(const float* __restrict__ Wg,
                              float* __restrict__ dout, int out_size) {
    int b = blockIdx.x;
    int lane = threadIdx.x;
    int e = lane & 7;
    int chunk = lane >> 3;
    float part = 0.f;
    const float* xa = g_xavg + b*D;
    for (int d = chunk*192; d < (chunk+1)*192; d++) part += xa[d] * Wg[d*NE + e];
    part += __shfl_down_sync(0xffffffffu, part, 16);
    part += __shfl_down_sync(0xffffffffu, part, 8);
    float lv[NE];
    #pragma unroll
    for (int i = 0; i < NE; i++) lv[i] = __shfl_sync(0xffffffffu, part, i);

    if (lane == 0) {
        float mx = lv[0];
        #pragma unroll
        for (int i = 1; i < NE; i++) mx = fmaxf(mx, lv[i]);
        float p[NE]; float sum = 0.f;
        #pragma unroll
        for (int i = 0; i < NE; i++) { p[i] = __expf(lv[i] - mx); sum += p[i]; }
        float inv = 1.0f / sum;
        #pragma unroll
        for (int i = 0; i < NE; i++) p[i] *= inv;
        int i0 = 0;
        #pragma unroll
        for (int i = 1; i < NE; i++) if (p[i] > p[i0]) i0 = i;
        int i1 = (i0 == 0) ? 1 : 0;
        #pragma unroll
        for (int i = 0; i < NE; i++) if (i != i0 && p[i] > p[i1]) i1 = i;
        g_sel[2*b] = i0; g_sel[2*b+1] = i1;
        if (out_size >= OUT_ELEMS + 2*NROWS) {
            dout[OUT_ELEMS + 2*b]             = p[i0];
            dout[OUT_ELEMS + 2*b + 1]         = p[i1];
            dout[OUT_ELEMS + NROWS + 2*b]     = (float)i0;
            dout[OUT_ELEMS + NROWS + 2*b + 1] = (float)i1;
        }
    }
}

// ---------------- kernel 3: group rows by expert (parallel, smem) -----------
__global__ void group_kernel() {
    __shared__ int ssel[NROWS];
    __shared__ int shist[NE];
    __shared__ int soff[NE];
    int t = threadIdx.x;
    if (t < NE) shist[t] = 0;
    __syncthreads();
    ssel[t] = g_sel[t];
    __syncthreads();
    atomicAdd(&shist[ssel[t]], 1);
    __syncthreads();
    if (t == 0) {
        int pos = 0, tiles = 0;
        for (int e = 0; e < NE; e++) {
            soff[e] = pos;
            int cnt = shist[e];
            for (int r = 0; r < cnt; r += 4) {
                g_tile_e[tiles] = e; g_tile_p0[tiles] = pos + r;
                g_tile_rows[tiles] = min(4, cnt - r); tiles++;
            }
            pos += cnt;
        }
        g_ntiles = tiles;
    }
    __syncthreads();
    // stable rank: #earlier rows with same expert
    int mysel = ssel[t], rank = 0;
    for (int m = 0; m < NROWS; m++)
        if (m < t && ssel[m] == mysel) rank++;
    g_perm[soff[mysel] + rank] = t;
}

// ---------------- tf32 mma.sync GEMM, KC=64, 2-stage cp.async ---------------
// PHASE 1: g_h = round(gelu(Xr_perm @ W1[e] + b1[e]));  K=768,  N=3072
// PHASE 2 (split-K=2): out[perm] += g_h @ W2[e](+b2 on kp0); K=1536/part
// CTA 128x256, 512 threads / 16 warps (2m x 8n), warp tile 64x32.
template<int PHASE>
__global__ __launch_bounds__(512, 1) void ffn_mma(
    const float* __restrict__ X,
    const float* __restrict__ W1, const float* __restrict__ b1,
    const float* __restrict__ W2, const float* __restrict__ b2,
    float* __restrict__ out)
{
    const int mt = blockIdx.x;
    if (mt >= g_ntiles) return;
    const int e     = g_tile_e[mt];
    const int p0    = g_tile_p0[mt];
    const int nrows = g_tile_rows[mt];
    const int kp    = (PHASE == 2) ? blockIdx.z : 0;
    const int NF    = (PHASE == 1) ? DFF : D;
    const int kbase = (PHASE == 2) ? kp * (DFF/2) : 0;
    const int NC    = ((PHASE == 1) ? D : DFF/2) / KC;
    const float* __restrict__ Bsrc = (PHASE == 1) ? (W1 + (size_t)e*D*DFF)
                                                  : (W2 + (size_t)e*DFF*D);
    const int n0 = blockIdx.y * NT;
    const int tid = threadIdx.x, wid = tid >> 5, lane = tid & 31;

    extern __shared__ float smf[];

    // ---- async loader assignment (512 threads) ----
    // A: 128 rows x 64 floats (16x16B); 4 thr/row, 4 segs each
    // B: 64 k-rows x 256 floats (64x16B); 8 thr/row, 8 segs each
    const int arow = tid >> 2, aseg = tid & 3;
    const int brow = tid >> 3, bseg = tid & 7;

    const float* aglob;
    {
        int r = ((arow >> 5) < nrows) ? arow : (arow & 31);  // clamp pad rows
        if (PHASE == 1) {
            int n = g_perm[p0 + (r >> 5)];
            aglob = g_xr + ((size_t)(n >> 1)*T + (r & 31)) * (size_t)D;
        } else {
            aglob = g_h + ((size_t)(p0*T + r)) * (size_t)DFF;
        }
    }
    const float* bglob = Bsrc + (size_t)brow*NF + n0;

    uint32_t sbase = (uint32_t)__cvta_generic_to_shared(smf);
    uint32_t aSts[STAGES], bSts[STAGES];
    #pragma unroll
    for (int s = 0; s < STAGES; s++) {
        aSts[s] = sbase + (s*STAGE_FLOATS + arow*AS_STRIDE)*4;
        bSts[s] = sbase + (s*STAGE_FLOATS + A_STAGE + brow*BS_STRIDE)*4;
    }

    #define ISSUE(k0, s) do {                                                 \
        _Pragma("unroll")                                                     \
        for (int i = 0; i < 4; i++)                                           \
            cp16(aSts[s] + (aseg*4 + i)*16, aglob + (k0) + (aseg*4 + i)*4);   \
        _Pragma("unroll")                                                     \
        for (int i = 0; i < 8; i++)                                           \
            cp16(bSts[s] + (bseg + 8*i)*16,                                   \
                 bglob + (size_t)(k0)*NF + (bseg + 8*i)*4);                   \
    } while (0)

    // ---- mma fragment bases (per stage); warp tile 64x32 ----
    const int wm = (wid & 1) * 64;
    const int wn = (wid >> 1) * 32;
    const int g  = lane >> 2;
    const int t  = lane & 3;
    const float* Abf[STAGES];
    const float* Bbf[STAGES];
    #pragma unroll
    for (int s = 0; s < STAGES; s++) {
        Abf[s] = smf + s*STAGE_FLOATS + (wm + g)*AS_STRIDE + t;
        Bbf[s] = smf + s*STAGE_FLOATS + A_STAGE + t*BS_STRIDE + wn + g;
    }

    float acc[4][4][4];
    #pragma unroll
    for (int i = 0; i < 4; i++)
        #pragma unroll
        for (int j = 0; j < 4; j++)
            #pragma unroll
            for (int q = 0; q < 4; q++) acc[i][j][q] = 0.f;

    // A data pre-rounded (g_xr / g_h stored rounded): raw bit reuse.
    // 8 k-slices per chunk -> long independent LDS+MMA stream per barrier.
    #define CONSUME(Ab, Bb) do {                                              \
        _Pragma("unroll")                                                     \
        for (int ks = 0; ks < 8; ks++) {                                      \
            uint32_t af[4][4], bf[4][2];                                      \
            _Pragma("unroll")                                                 \
            for (int mi = 0; mi < 4; mi++) {                                  \
                af[mi][0] = __float_as_uint((Ab)[mi*16*AS_STRIDE + ks*8]);    \
                af[mi][1] = __float_as_uint((Ab)[mi*16*AS_STRIDE + ks*8 + 8*AS_STRIDE]); \
                af[mi][2] = __float_as_uint((Ab)[mi*16*AS_STRIDE + ks*8 + 4]);\
                af[mi][3] = __float_as_uint((Ab)[mi*16*AS_STRIDE + ks*8 + 8*AS_STRIDE + 4]); \
            }                                                                 \
            _Pragma("unroll")                                                 \
            for (int ni = 0; ni < 4; ni++) {                                  \
                bf[ni][0] = cvt_tf32((Bb)[ks*8*BS_STRIDE + ni*8]);            \
                bf[ni][1] = cvt_tf32((Bb)[ks*8*BS_STRIDE + ni*8 + 4*BS_STRIDE]); \
            }                                                                 \
            _Pragma("unroll")                                                 \
            for (int mi = 0; mi < 4; mi++)                                    \
                _Pragma("unroll")                                             \
                for (int ni = 0; ni < 4; ni++)                                \
                    mma_tf32(acc[mi][ni], af[mi][0], af[mi][1], af[mi][2],    \
                             af[mi][3], bf[ni][0], bf[ni][1]);                \
        }                                                                     \
    } while (0)

    // ---- prologue: chunk 0 in flight ----
    ISSUE(kbase, 0);
    asm volatile("cp.async.commit_group;" ::: "memory");

    // ---- main loop: one barrier per KC=64 chunk ----
    for (int c = 0; c < NC; c++) {
        asm volatile("cp.async.wait_group 0;" ::: "memory");  // chunk c landed
        __syncthreads();          // all threads see it; consume(c-1) done by all
        if (c + 1 < NC) ISSUE(kbase + (c + 1)*KC, (c + 1) & 1);
        asm volatile("cp.async.commit_group;" ::: "memory");
        if (c & 1) CONSUME(Abf[1], Bbf[1]);
        else       CONSUME(Abf[0], Bbf[0]);
    }

    // ---- epilogue ----
    const float* bias = (PHASE == 1) ? (b1 + e*DFF + n0) : (b2 + e*D + n0);
    #pragma unroll
    for (int mi = 0; mi < 4; mi++) {
        #pragma unroll
        for (int h = 0; h < 2; h++) {
            int r = wm + 16*mi + g + 8*h;
            int br = r >> 5;
            if (br >= nrows) continue;
            if (PHASE == 1) {
                float* dst = g_h + ((size_t)(p0*T + r)) * (size_t)DFF + n0;
                #pragma unroll
                for (int ni = 0; ni < 4; ni++) {
                    int col = wn + 8*ni + 2*t;
                    float v0 = gelu_exact(acc[mi][ni][2*h + 0] + bias[col]);
                    float v1 = gelu_exact(acc[mi][ni][2*h + 1] + bias[col + 1]);
                    uint2 w = make_uint2(cvt_tf32(v0), cvt_tf32(v1));
                    *(uint2*)(dst + col) = w;
                }
            } else {
                int n = g_perm[p0 + br];
                float* dst = out + ((size_t)n*T + (r & 31)) * (size_t)D + n0;
                #pragma unroll
                for (int ni = 0; ni < 4; ni++) {
                    int col = wn + 8*ni + 2*t;
                    float v0 = acc[mi][ni][2*h + 0];
                    float v1 = acc[mi][ni][2*h + 1];
                    if (kp == 0) { v0 += bias[col]; v1 += bias[col + 1]; }
                    // exactly 2 atomic contributions per element onto 0-init:
                    // order-invariant -> deterministic
                    atomicAdd(dst + col,     v0);
                    atomicAdd(dst + col + 1, v1);
                }
            }
        }
    }
    #undef ISSUE
    #undef CONSUME
}

// ---------------- launch ----------------------------------------------------
extern "C" void kernel_launch(void* const* d_in, const int* in_sizes, int n_in,
                              void* d_out, int out_size) {
    const float* x  = (const float*)d_in[0];
    const float* Wg = (const float*)d_in[2];
    const float* W1 = (const float*)d_in[3];
    const float* b1 = (const float*)d_in[4];
    const float* W2 = (const float*)d_in[5];
    const float* b2 = (const float*)d_in[6];
    float* out = (float*)d_out;

    cudaFuncSetAttribute(ffn_mma<1>, cudaFuncAttributeMaxDynamicSharedMemorySize, SMEM_BYTES);
    cudaFuncSetAttribute(ffn_mma<2>, cudaFuncAttributeMaxDynamicSharedMemorySize, SMEM_BYTES);

    cudaMemsetAsync(out, 0, (size_t)OUT_ELEMS * sizeof(float));
    round_x_kernel<<<(BZ*T*D/4 + 255)/256, 256>>>(x);
    avg_kernel<<<BZ, 256>>>(x);
    router_kernel<<<BZ, 32>>>(Wg, out, out_size);
    group_kernel<<<1, NROWS>>>();
    ffn_mma<1><<<dim3(MAX_TILES, DFF/NT),  512, SMEM_BYTES>>>(x, W1, b1, W2, b2, out);
    ffn_mma<2><<<dim3(MAX_TILES, D/NT, 2), 512, SMEM_BYTES>>>(x, W1, b1, W2, b2, out);
}

// round 10
// speedup vs baseline: 1.4542x; 1.3790x over previous
#include <cuda_runtime.h>
#include <cuda_fp16.h>
#include <math.h>
#include <stdint.h>

#define BZ   128
#define T    32
#define D    768
#define DFF  3072
#define NE   8
#define NROWS 256
#define OUT_ELEMS (NROWS*T*D)
#define MAX_TILES 72

#define NT        256                 // CTA N tile
#define KC        64                  // K chunk
#define AS_H      88                  // A smem row stride (halves): 176B, LDSM-clean
#define BS_H      264                 // B smem k-row stride (halves): 528B, LDSM-clean
#define A_STAGE_H (128*AS_H)          // 11264 halves
#define B_STAGE_H (KC*BS_H)           // 16896 halves
#define STAGE_H   (A_STAGE_H + B_STAGE_H)
#define SMEM_BYTES (2*STAGE_H*2)      // 112640 B

// ---------------- scratch ---------------------------------------------------
__device__ float g_xavg[BZ*D];
__device__ int   g_sel[NROWS];
__device__ int   g_perm[NROWS];
__device__ int   g_tile_e[MAX_TILES];
__device__ int   g_tile_p0[MAX_TILES];
__device__ int   g_tile_rows[MAX_TILES];
__device__ int   g_ntiles;
__device__ __half g_xh[(size_t)BZ*T*D];        // fp16 copy of x
__device__ __half g_h[(size_t)NROWS*T*DFF];    // fp16 intermediate, grouped

__device__ __forceinline__ float gelu_exact(float v) {
    return 0.5f * v * (1.0f + erff(v * 0.70710678118654752f));
}
__device__ __forceinline__ uint32_t pack_h2(float lo, float hi) {
    uint32_t d;
    asm("cvt.rn.f16x2.f32 %0, %1, %2;" : "=r"(d) : "f"(hi), "f"(lo));
    return d;
}
__device__ __forceinline__ void mma_f16(float* c,
                                        uint32_t a0, uint32_t a1, uint32_t a2, uint32_t a3,
                                        uint32_t b0, uint32_t b1) {
    asm volatile(
        "mma.sync.aligned.m16n8k16.row.col.f32.f16.f16.f32 "
        "{%0,%1,%2,%3}, {%4,%5,%6,%7}, {%8,%9}, {%0,%1,%2,%3};"
        : "+f"(c[0]), "+f"(c[1]), "+f"(c[2]), "+f"(c[3])
        : "r"(a0), "r"(a1), "r"(a2), "r"(a3), "r"(b0), "r"(b1));
}
__device__ __forceinline__ void ldsm4(uint32_t* r, uint32_t addr) {
    asm volatile("ldmatrix.sync.aligned.m8n8.x4.shared.b16 {%0,%1,%2,%3}, [%4];"
        : "=r"(r[0]), "=r"(r[1]), "=r"(r[2]), "=r"(r[3]) : "r"(addr));
}
__device__ __forceinline__ void ldsm4t(uint32_t* r, uint32_t addr) {
    asm volatile("ldmatrix.sync.aligned.m8n8.x4.trans.shared.b16 {%0,%1,%2,%3}, [%4];"
        : "=r"(r[0]), "=r"(r[1]), "=r"(r[2]), "=r"(r[3]) : "r"(addr));
}
__device__ __forceinline__ void cp16(uint32_t saddr, const void* g) {
    asm volatile("cp.async.cg.shared.global [%0], [%1], 16;" :: "r"(saddr), "l"(g));
}

// ---------------- kernel 0: x -> fp16 ---------------------------------------
__global__ void half_x_kernel(const float* __restrict__ x) {
    int i = blockIdx.x * blockDim.x + threadIdx.x;
    const int n4 = BZ*T*D/4;
    if (i < n4) {
        float4 v = ((const float4*)x)[i];
        uint2 r = make_uint2(pack_h2(v.x, v.y), pack_h2(v.z, v.w));
        ((uint2*)g_xh)[i] = r;
    }
}

// ---------------- kernel 1: x_avg (fp32) ------------------------------------
__global__ void avg_kernel(const float* __restrict__ x) {
    int b = blockIdx.x;
    for (int d = threadIdx.x; d < D; d += blockDim.x) {
        float s = 0.f;
        #pragma unroll
        for (int t = 0; t < T; t++) s += x[((size_t)b*T + t)*D + d];
        g_xavg[b*D + d] = s * (1.0f / T);
    }
}

// ---------------- kernel 2: router ------------------------------------------
__global__ void router_kernel(const float* __restrict__ Wg,
                              float* __restrict__ dout, int out_size) {
    int b = blockIdx.x;
    int lane = threadIdx.x;
    int e = lane & 7;
    int chunk = lane >> 3;
    float part = 0.f;
    const float* xa = g_xavg + b*D;
    for (int d = chunk*192; d < (chunk+1)*192; d++) part += xa[d] * Wg[d*NE + e];
    part += __shfl_down_sync(0xffffffffu, part, 16);
    part += __shfl_down_sync(0xffffffffu, part, 8);
    float lv[NE];
    #pragma unroll
    for (int i = 0; i < NE; i++) lv[i] = __shfl_sync(0xffffffffu, part, i);

    if (lane == 0) {
        float mx = lv[0];
        #pragma unroll
        for (int i = 1; i < NE; i++) mx = fmaxf(mx, lv[i]);
        float p[NE]; float sum = 0.f;
        #pragma unroll
        for (int i = 0; i < NE; i++) { p[i] = __expf(lv[i] - mx); sum += p[i]; }
        float inv = 1.0f / sum;
        #pragma unroll
        for (int i = 0; i < NE; i++) p[i] *= inv;
        int i0 = 0;
        #pragma unroll
        for (int i = 1; i < NE; i++) if (p[i] > p[i0]) i0 = i;
        int i1 = (i0 == 0) ? 1 : 0;
        #pragma unroll
        for (int i = 0; i < NE; i++) if (i != i0 && p[i] > p[i1]) i1 = i;
        g_sel[2*b] = i0; g_sel[2*b+1] = i1;
        if (out_size >= OUT_ELEMS + 2*NROWS) {
            dout[OUT_ELEMS + 2*b]             = p[i0];
            dout[OUT_ELEMS + 2*b + 1]         = p[i1];
            dout[OUT_ELEMS + NROWS + 2*b]     = (float)i0;
            dout[OUT_ELEMS + NROWS + 2*b + 1] = (float)i1;
        }
    }
}

// ---------------- kernel 3: group rows by expert ----------------------------
__global__ void group_kernel() {
    __shared__ int ssel[NROWS];
    __shared__ int shist[NE];
    __shared__ int soff[NE];
    int t = threadIdx.x;
    if (t < NE) shist[t] = 0;
    __syncthreads();
    ssel[t] = g_sel[t];
    __syncthreads();
    atomicAdd(&shist[ssel[t]], 1);
    __syncthreads();
    if (t == 0) {
        int pos = 0, tiles = 0;
        for (int e = 0; e < NE; e++) {
            soff[e] = pos;
            int cnt = shist[e];
            for (int r = 0; r < cnt; r += 4) {
                g_tile_e[tiles] = e; g_tile_p0[tiles] = pos + r;
                g_tile_rows[tiles] = min(4, cnt - r); tiles++;
            }
            pos += cnt;
        }
        g_ntiles = tiles;
    }
    __syncthreads();
    int mysel = ssel[t], rank = 0;
    for (int m = 0; m < NROWS; m++)
        if (m < t && ssel[m] == mysel) rank++;
    g_perm[soff[mysel] + rank] = t;
}

// ---------------- fp16 m16n8k16 GEMM, ldmatrix, KC=64, 2-stage --------------
// PHASE 1: g_h = fp16(gelu(Xh_perm @ W1[e] + b1[e]));  K=768,  N=3072
// PHASE 2 (split-K=2): out[perm] += g_h @ W2[e](+b2 on kp0); K=1536/part
// CTA 128x256, 512 threads / 16 warps (2m x 8n), warp tile 64x32.
template<int PHASE>
__global__ __launch_bounds__(512, 1) void ffn_mma(
    const float* __restrict__ X,
    const float* __restrict__ W1, const float* __restrict__ b1,
    const float* __restrict__ W2, const float* __restrict__ b2,
    float* __restrict__ out)
{
    const int mt = blockIdx.x;
    if (mt >= g_ntiles) return;
    const int e     = g_tile_e[mt];
    const int p0    = g_tile_p0[mt];
    const int nrows = g_tile_rows[mt];
    const int kp    = (PHASE == 2) ? blockIdx.z : 0;
    const int NF    = (PHASE == 1) ? DFF : D;
    const int kbase = (PHASE == 2) ? kp * (DFF/2) : 0;
    const int NC    = ((PHASE == 1) ? D : DFF/2) / KC;
    const float* __restrict__ Bsrc = (PHASE == 1) ? (W1 + (size_t)e*D*DFF)
                                                  : (W2 + (size_t)e*DFF*D);
    const int n0 = blockIdx.y * NT;
    const int tid = threadIdx.x, wid = tid >> 5, lane = tid & 31;

    extern __shared__ __half smh[];
    uint32_t sbase = (uint32_t)__cvta_generic_to_shared(smh);

    // ---- A loader: fp16 via cp.async. 128 rows x 64 halves = 8 segs/row ----
    const int arow = tid >> 2, aseg = (tid & 3) * 2;   // 2 segs per thread
    const __half* aglob;
    {
        int r = ((arow >> 5) < nrows) ? arow : (arow & 31);
        if (PHASE == 1) {
            int n = g_perm[p0 + (r >> 5)];
            aglob = g_xh + ((size_t)(n >> 1)*T + (r & 31)) * (size_t)D;
        } else {
            aglob = g_h + ((size_t)(p0*T + r)) * (size_t)DFF;
        }
    }
    uint32_t aSts[2];
    aSts[0] = sbase + (0*STAGE_H + arow*AS_H)*2;
    aSts[1] = sbase + (1*STAGE_H + arow*AS_H)*2;

    #define ISSUE_A(k0, s) do {                                               \
        cp16(aSts[s] + (aseg+0)*16, aglob + (k0) + (aseg+0)*8);               \
        cp16(aSts[s] + (aseg+1)*16, aglob + (k0) + (aseg+1)*8);               \
    } while (0)

    // ---- B loader: LDG fp32 -> cvt f16x2 -> STS. half-chunk = 32 k-rows ----
    const int bkr = tid >> 4;            // 0..31 k-row within half
    const int bns = (tid & 15) * 16;     // 16 floats per thread
    const float* bglob = Bsrc + (size_t)bkr*NF + n0 + bns;
    float4 bs4[4];

    #define LDG_B(k0, h) do {                                                 \
        const float* p = bglob + (size_t)((k0) + (h)*32)*NF;                  \
        bs4[0] = *(const float4*)(p);     bs4[1] = *(const float4*)(p + 4);   \
        bs4[2] = *(const float4*)(p + 8); bs4[3] = *(const float4*)(p + 12);  \
    } while (0)

    #define STS_B(s, h) do {                                                  \
        uint32_t base = sbase + ((s)*STAGE_H + A_STAGE_H                      \
                         + ((h)*32 + bkr)*BS_H + bns)*2;                      \
        _Pragma("unroll")                                                     \
        for (int i = 0; i < 4; i++) {                                         \
            uint32_t u0 = pack_h2(bs4[i].x, bs4[i].y);                        \
            uint32_t u1 = pack_h2(bs4[i].z, bs4[i].w);                        \
            asm volatile("st.shared.v2.u32 [%0], {%1, %2};"                   \
                :: "r"(base + i*8), "r"(u0), "r"(u1) : "memory");             \
        }                                                                     \
    } while (0)

    // ---- ldmatrix lane bases ----
    const int wm = (wid & 1) * 64;
    const int wn = (wid >> 1) * 32;
    const int lm = lane >> 3;            // matrix index 0..3
    const int lr = lane & 7;
    // A: matrix -> row += (lm&1)*8, col += (lm>>1)*8
    uint32_t aLd[2];
    {
        uint32_t off = ((wm + (lm & 1)*8 + lr)*AS_H + (lm >> 1)*8) * 2;
        aLd[0] = sbase + 0*STAGE_H*2 + off;
        aLd[1] = sbase + 1*STAGE_H*2 + off;
    }
    // B: matrix -> k += (lm&1)*8, n += (lm>>1)*8
    uint32_t bLd[2];
    {
        uint32_t off = (A_STAGE_H + ((lm & 1)*8 + lr)*BS_H + wn + (lm >> 1)*8) * 2;
        bLd[0] = sbase + 0*STAGE_H*2 + off;
        bLd[1] = sbase + 1*STAGE_H*2 + off;
    }

    float acc[4][4][4];
    #pragma unroll
    for (int i = 0; i < 4; i++)
        #pragma unroll
        for (int j = 0; j < 4; j++)
            #pragma unroll
            for (int q = 0; q < 4; q++) acc[i][j][q] = 0.f;

    // consume k16-slices ks0..ks0+1 of stage s
    #define CONSUME_HALF(s, ks0) do {                                         \
        _Pragma("unroll")                                                     \
        for (int ks = (ks0); ks < (ks0) + 2; ks++) {                          \
            uint32_t af[4][4], bf[2][4];                                      \
            _Pragma("unroll")                                                 \
            for (int mi = 0; mi < 4; mi++)                                    \
                ldsm4(af[mi], aLd[s] + (mi*16*AS_H + ks*16)*2);               \
            _Pragma("unroll")                                                 \
            for (int nj = 0; nj < 2; nj++)                                    \
                ldsm4t(bf[nj], bLd[s] + (ks*16*BS_H + nj*16)*2);              \
            _Pragma("unroll")                                                 \
            for (int mi = 0; mi < 4; mi++) {                                  \
                _Pragma("unroll")                                             \
                for (int nj = 0; nj < 2; nj++) {                              \
                    mma_f16(acc[mi][2*nj],   af[mi][0], af[mi][1], af[mi][2], \
                            af[mi][3], bf[nj][0], bf[nj][1]);                 \
                    mma_f16(acc[mi][2*nj+1], af[mi][0], af[mi][1], af[mi][2], \
                            af[mi][3], bf[nj][2], bf[nj][3]);                 \
                }                                                             \
            }                                                                 \
        }                                                                     \
    } while (0)

    // ---- prologue: B(0) + A(0) into stage 0 ----
    LDG_B(kbase, 0); STS_B(0, 0);
    LDG_B(kbase, 1); STS_B(0, 1);
    ISSUE_A(kbase, 0);
    asm volatile("cp.async.commit_group;" ::: "memory");

    // ---- main loop: one barrier per chunk ----
    for (int c = 0; c < NC; c++) {
        const int s = c & 1;
        const bool more = (c + 1 < NC);
        const int knext = kbase + (c + 1)*KC;
        asm volatile("cp.async.wait_group 0;" ::: "memory");
        __syncthreads();     // A(c)+B(c) visible to all; stage s^1 free
        if (more) {
            ISSUE_A(knext, s ^ 1);
            asm volatile("cp.async.commit_group;" ::: "memory");
            LDG_B(knext, 0);
        }
        CONSUME_HALF(s, 0);
        if (more) { STS_B(s ^ 1, 0); LDG_B(knext, 1); }
        CONSUME_HALF(s, 2);
        if (more) STS_B(s ^ 1, 1);
    }

    // ---- epilogue ----
    const int g = lane >> 2, t4 = lane & 3;
    const float* bias = (PHASE == 1) ? (b1 + e*DFF + n0) : (b2 + e*D + n0);
    #pragma unroll
    for (int mi = 0; mi < 4; mi++) {
        #pragma unroll
        for (int h = 0; h < 2; h++) {
            int r = wm + 16*mi + g + 8*h;
            int br = r >> 5;
            if (br >= nrows) continue;
            if (PHASE == 1) {
                __half* dst = g_h + ((size_t)(p0*T + r)) * (size_t)DFF + n0;
                #pragma unroll
                for (int ni = 0; ni < 4; ni++) {
                    int col = wn + 8*ni + 2*t4;
                    float v0 = gelu_exact(acc[mi][ni][2*h + 0] + bias[col]);
                    float v1 = gelu_exact(acc[mi][ni][2*h + 1] + bias[col + 1]);
                    *(uint32_t*)(dst + col) = pack_h2(v0, v1);
                }
            } else {
                int n = g_perm[p0 + br];
                float* dst = out + ((size_t)n*T + (r & 31)) * (size_t)D + n0;
                #pragma unroll
                for (int ni = 0; ni < 4; ni++) {
                    int col = wn + 8*ni + 2*t4;
                    float v0 = acc[mi][ni][2*h + 0];
                    float v1 = acc[mi][ni][2*h + 1];
                    if (kp == 0) { v0 += bias[col]; v1 += bias[col + 1]; }
                    atomicAdd(dst + col,     v0);   // 2 contributions onto 0:
                    atomicAdd(dst + col + 1, v1);   // order-invariant
                }
            }
        }
    }
    #undef ISSUE_A
    #undef LDG_B
    #undef STS_B
    #undef CONSUME_HALF
}

// ---------------- launch ----------------------------------------------------
extern "C" void kernel_launch(void* const* d_in, const int* in_sizes, int n_in,
                              void* d_out, int out_size) {
    const float* x  = (const float*)d_in[0];
    const float* Wg = (const float*)d_in[2];
    const float* W1 = (const float*)d_in[3];
    const float* b1 = (const float*)d_in[4];
    const float* W2 = (const float*)d_in[5];
    const float* b2 = (const float*)d_in[6];
    float* out = (float*)d_out;

    cudaFuncSetAttribute(ffn_mma<1>, cudaFuncAttributeMaxDynamicSharedMemorySize, SMEM_BYTES);
    cudaFuncSetAttribute(ffn_mma<2>, cudaFuncAttributeMaxDynamicSharedMemorySize, SMEM_BYTES);

    cudaMemsetAsync(out, 0, (size_t)OUT_ELEMS * sizeof(float));
    half_x_kernel<<<(BZ*T*D/4 + 255)/256, 256>>>(x);
    avg_kernel<<<BZ, 256>>>(x);
    router_kernel<<<BZ, 32>>>(Wg, out, out_size);
    group_kernel<<<1, NROWS>>>();
    ffn_mma<1><<<dim3(MAX_TILES, DFF/NT),  512, SMEM_BYTES>>>(x, W1, b1, W2, b2, out);
    ffn_mma<2><<<dim3(MAX_TILES, D/NT, 2), 512, SMEM_BYTES>>>(x, W1, b1, W2, b2, out);
}

// round 11
// speedup vs baseline: 1.8048x; 1.2411x over previous
#include <cuda_runtime.h>
#include <cuda_fp16.h>
#include <math.h>
#include <stdint.h>

#define BZ   128
#define T    32
#define D    768
#define DFF  3072
#define NE   8
#define NROWS 256
#define OUT_ELEMS (NROWS*T*D)
#define MAX_TILES 72

#define NT        256                 // CTA N tile
#define KC        64                  // K chunk
#define STAGES    3
#define AS_H      72                  // A smem row stride (halves), LDSM-clean
#define BS_H      264                 // B smem k-row stride (halves), LDSM-clean
#define A_STAGE_H (128*AS_H)          // 9216 halves
#define B_STAGE_H (KC*BS_H)           // 16896 halves
#define STAGE_H   (A_STAGE_H + B_STAGE_H)      // 26112 halves
#define SMEM_BYTES (STAGES*STAGE_H*2)          // 156672 B

// ---------------- scratch ---------------------------------------------------
__device__ float g_xavg_unused;  // (avg fused into router now)
__device__ int   g_sel[NROWS];
__device__ int   g_perm[NROWS];
__device__ int   g_tile_e[MAX_TILES];
__device__ int   g_tile_p0[MAX_TILES];
__device__ int   g_tile_rows[MAX_TILES];
__device__ int   g_ntiles;
__device__ __half g_xh[(size_t)BZ*T*D];        // fp16 copy of x
__device__ __half g_h[(size_t)NROWS*T*DFF];    // fp16 intermediate, grouped
__device__ __half g_w1h[(size_t)NE*D*DFF];     // fp16 W1
__device__ __half g_w2h[(size_t)NE*DFF*D];     // fp16 W2

__device__ __forceinline__ float gelu_exact(float v) {
    return 0.5f * v * (1.0f + erff(v * 0.70710678118654752f));
}
__device__ __forceinline__ uint32_t pack_h2(float lo, float hi) {
    uint32_t d;
    asm("cvt.rn.f16x2.f32 %0, %1, %2;" : "=r"(d) : "f"(hi), "f"(lo));
    return d;
}
__device__ __forceinline__ void mma_f16(float* c,
                                        uint32_t a0, uint32_t a1, uint32_t a2, uint32_t a3,
                                        uint32_t b0, uint32_t b1) {
    asm volatile(
        "mma.sync.aligned.m16n8k16.row.col.f32.f16.f16.f32 "
        "{%0,%1,%2,%3}, {%4,%5,%6,%7}, {%8,%9}, {%0,%1,%2,%3};"
        : "+f"(c[0]), "+f"(c[1]), "+f"(c[2]), "+f"(c[3])
        : "r"(a0), "r"(a1), "r"(a2), "r"(a3), "r"(b0), "r"(b1));
}
__device__ __forceinline__ void ldsm4(uint32_t* r, uint32_t addr) {
    asm volatile("ldmatrix.sync.aligned.m8n8.x4.shared.b16 {%0,%1,%2,%3}, [%4];"
        : "=r"(r[0]), "=r"(r[1]), "=r"(r[2]), "=r"(r[3]) : "r"(addr));
}
__device__ __forceinline__ void ldsm4t(uint32_t* r, uint32_t addr) {
    asm volatile("ldmatrix.sync.aligned.m8n8.x4.trans.shared.b16 {%0,%1,%2,%3}, [%4];"
        : "=r"(r[0]), "=r"(r[1]), "=r"(r[2]), "=r"(r[3]) : "r"(addr));
}
__device__ __forceinline__ void cp16(uint32_t saddr, const void* g) {
    asm volatile("cp.async.cg.shared.global [%0], [%1], 16;" :: "r"(saddr), "l"(g));
}

// ---------------- kernel 0a: x -> fp16 --------------------------------------
__global__ void half_x_kernel(const float* __restrict__ x) {
    int i = blockIdx.x * blockDim.x + threadIdx.x;
    const int n4 = BZ*T*D/4;
    if (i < n4) {
        float4 v = ((const float4*)x)[i];
        ((uint2*)g_xh)[i] = make_uint2(pack_h2(v.x, v.y), pack_h2(v.z, v.w));
    }
}

// ---------------- kernel 0b: W1,W2 -> fp16 ----------------------------------
__global__ void wcvt_kernel(const float* __restrict__ W1,
                            const float* __restrict__ W2) {
    size_t i = (size_t)blockIdx.x * blockDim.x + threadIdx.x;
    const size_t n4 = (size_t)NE*D*DFF/4;
    if (i < n4) {
        float4 a = ((const float4*)W1)[i];
        ((uint2*)g_w1h)[i] = make_uint2(pack_h2(a.x, a.y), pack_h2(a.z, a.w));
        float4 b = ((const float4*)W2)[i];
        ((uint2*)g_w2h)[i] = make_uint2(pack_h2(b.x, b.y), pack_h2(b.z, b.w));
    }
}

// ---------------- kernel 1: fused avg + router ------------------------------
__global__ void avg_router_kernel(const float* __restrict__ x,
                                  const float* __restrict__ Wg,
                                  float* __restrict__ dout, int out_size) {
    __shared__ float xa[D];
    int b = blockIdx.x;
    for (int d = threadIdx.x; d < D; d += blockDim.x) {
        float s = 0.f;
        #pragma unroll
        for (int t = 0; t < T; t++) s += x[((size_t)b*T + t)*D + d];
        xa[d] = s * (1.0f / T);
    }
    __syncthreads();
    if (threadIdx.x < 32) {
        int lane = threadIdx.x;
        int e = lane & 7;
        int chunk = lane >> 3;
        float part = 0.f;
        for (int d = chunk*192; d < (chunk+1)*192; d++) part += xa[d] * Wg[d*NE + e];
        part += __shfl_down_sync(0xffffffffu, part, 16);
        part += __shfl_down_sync(0xffffffffu, part, 8);
        float lv[NE];
        #pragma unroll
        for (int i = 0; i < NE; i++) lv[i] = __shfl_sync(0xffffffffu, part, i);
        if (lane == 0) {
            float mx = lv[0];
            #pragma unroll
            for (int i = 1; i < NE; i++) mx = fmaxf(mx, lv[i]);
            float p[NE]; float sum = 0.f;
            #pragma unroll
            for (int i = 0; i < NE; i++) { p[i] = __expf(lv[i] - mx); sum += p[i]; }
            float inv = 1.0f / sum;
            #pragma unroll
            for (int i = 0; i < NE; i++) p[i] *= inv;
            int i0 = 0;
            #pragma unroll
            for (int i = 1; i < NE; i++) if (p[i] > p[i0]) i0 = i;
            int i1 = (i0 == 0) ? 1 : 0;
            #pragma unroll
            for (int i = 0; i < NE; i++) if (i != i0 && p[i] > p[i1]) i1 = i;
            g_sel[2*b] = i0; g_sel[2*b+1] = i1;
            if (out_size >= OUT_ELEMS + 2*NROWS) {
                dout[OUT_ELEMS + 2*b]             = p[i0];
                dout[OUT_ELEMS + 2*b + 1]         = p[i1];
                dout[OUT_ELEMS + NROWS + 2*b]     = (float)i0;
                dout[OUT_ELEMS + NROWS + 2*b + 1] = (float)i1;
            }
        }
    }
}

// ---------------- kernel 2: group rows by expert ----------------------------
__global__ void group_kernel() {
    __shared__ int ssel[NROWS];
    __shared__ int shist[NE];
    __shared__ int soff[NE];
    int t = threadIdx.x;
    if (t < NE) shist[t] = 0;
    __syncthreads();
    ssel[t] = g_sel[t];
    __syncthreads();
    atomicAdd(&shist[ssel[t]], 1);
    __syncthreads();
    if (t == 0) {
        int pos = 0, tiles = 0;
        for (int e = 0; e < NE; e++) {
            soff[e] = pos;
            int cnt = shist[e];
            for (int r = 0; r < cnt; r += 4) {
                g_tile_e[tiles] = e; g_tile_p0[tiles] = pos + r;
                g_tile_rows[tiles] = min(4, cnt - r); tiles++;
            }
            pos += cnt;
        }
        g_ntiles = tiles;
    }
    __syncthreads();
    int mysel = ssel[t], rank = 0;
    for (int m = 0; m < NROWS; m++)
        if (m < t && ssel[m] == mysel) rank++;
    g_perm[soff[mysel] + rank] = t;
}

// ---------------- fp16 m16n8k16 GEMM, all-cp.async 3-stage ------------------
// PHASE 1: g_h = fp16(gelu(Xh_perm @ W1h[e] + b1[e]));  K=768,  N=3072
// PHASE 2 (split-K=2): out[perm] += g_h @ W2h[e](+b2 on kp0); K=1536/part
// CTA 128x256, 512 threads / 16 warps (2m x 8n), warp tile 64x32.
template<int PHASE>
__global__ __launch_bounds__(512, 1) void ffn_mma(
    const float* __restrict__ b1f, const float* __restrict__ b2f,
    float* __restrict__ out)
{
    const int mt = blockIdx.x;
    if (mt >= g_ntiles) return;
    const int e     = g_tile_e[mt];
    const int p0    = g_tile_p0[mt];
    const int nrows = g_tile_rows[mt];
    const int kp    = (PHASE == 2) ? blockIdx.z : 0;
    const int NF    = (PHASE == 1) ? DFF : D;
    const int kbase = (PHASE == 2) ? kp * (DFF/2) : 0;
    const int NC    = ((PHASE == 1) ? D : DFF/2) / KC;
    const __half* __restrict__ Bsrc = (PHASE == 1) ? (g_w1h + (size_t)e*D*DFF)
                                                   : (g_w2h + (size_t)e*DFF*D);
    const int n0 = blockIdx.y * NT;
    const int tid = threadIdx.x, wid = tid >> 5, lane = tid & 31;

    extern __shared__ __half smh[];
    uint32_t sbase = (uint32_t)__cvta_generic_to_shared(smh);

    // ---- A loader: 128 rows x 64 halves (8x16B segs), 4 thr/row x 2 segs ----
    const int arow = tid >> 2, aseg = (tid & 3) * 2;
    const __half* aglob;
    {
        int r = ((arow >> 5) < nrows) ? arow : (arow & 31);
        if (PHASE == 1) {
            int n = g_perm[p0 + (r >> 5)];
            aglob = g_xh + ((size_t)(n >> 1)*T + (r & 31)) * (size_t)D;
        } else {
            aglob = g_h + ((size_t)(p0*T + r)) * (size_t)DFF;
        }
    }
    // ---- B loader: 64 k-rows x 256 halves (32x16B segs), 8 thr/row x 4 segs
    const int brow = tid >> 3, bseg = tid & 7;
    const __half* bglob = Bsrc + (size_t)brow*NF + n0;

    uint32_t aSts[STAGES], bSts[STAGES];
    #pragma unroll
    for (int s = 0; s < STAGES; s++) {
        aSts[s] = sbase + (s*STAGE_H + arow*AS_H)*2;
        bSts[s] = sbase + (s*STAGE_H + A_STAGE_H + brow*BS_H)*2;
    }

    #define ISSUE(k0, s) do {                                                 \
        cp16(aSts[s] + (aseg+0)*16, aglob + (k0) + (aseg+0)*8);               \
        cp16(aSts[s] + (aseg+1)*16, aglob + (k0) + (aseg+1)*8);               \
        _Pragma("unroll")                                                     \
        for (int i = 0; i < 4; i++)                                           \
            cp16(bSts[s] + (bseg + 8*i)*16,                                   \
                 bglob + (size_t)(k0)*NF + (bseg + 8*i)*8);                   \
    } while (0)

    // ---- ldmatrix lane bases ----
    const int wm = (wid & 1) * 64;
    const int wn = (wid >> 1) * 32;
    const int lm = lane >> 3;
    const int lr = lane & 7;
    uint32_t aLd[STAGES], bLd[STAGES];
    #pragma unroll
    for (int s = 0; s < STAGES; s++) {
        aLd[s] = sbase + (s*STAGE_H + (wm + (lm & 1)*8 + lr)*AS_H + (lm >> 1)*8)*2;
        bLd[s] = sbase + (s*STAGE_H + A_STAGE_H
                          + ((lm & 1)*8 + lr)*BS_H + wn + (lm >> 1)*8)*2;
    }

    float acc[4][4][4];
    #pragma unroll
    for (int i = 0; i < 4; i++)
        #pragma unroll
        for (int j = 0; j < 4; j++)
            #pragma unroll
            for (int q = 0; q < 4; q++) acc[i][j][q] = 0.f;

    #define CONSUME(aL, bL) do {                                              \
        _Pragma("unroll")                                                     \
        for (int ks = 0; ks < 4; ks++) {                                      \
            uint32_t af[4][4], bf[2][4];                                      \
            _Pragma("unroll")                                                 \
            for (int mi = 0; mi < 4; mi++)                                    \
                ldsm4(af[mi], (aL) + (mi*16*AS_H + ks*16)*2);                 \
            _Pragma("unroll")                                                 \
            for (int nj = 0; nj < 2; nj++)                                    \
                ldsm4t(bf[nj], (bL) + (ks*16*BS_H + nj*16)*2);                \
            _Pragma("unroll")                                                 \
            for (int mi = 0; mi < 4; mi++) {                                  \
                _Pragma("unroll")                                             \
                for (int nj = 0; nj < 2; nj++) {                              \
                    mma_f16(acc[mi][2*nj],   af[mi][0], af[mi][1], af[mi][2], \
                            af[mi][3], bf[nj][0], bf[nj][1]);                 \
                    mma_f16(acc[mi][2*nj+1], af[mi][0], af[mi][1], af[mi][2], \
                            af[mi][3], bf[nj][2], bf[nj][3]);                 \
                }                                                             \
            }                                                                 \
        }                                                                     \
    } while (0)

    // ---- prologue: chunks 0,1 in flight ----
    ISSUE(kbase, 0);
    asm volatile("cp.async.commit_group;" ::: "memory");
    ISSUE(kbase + KC, 1);
    asm volatile("cp.async.commit_group;" ::: "memory");

    // ---- main loop: one barrier per chunk, loads fully overlapped ----
    for (int c = 0; c < NC; c++) {
        asm volatile("cp.async.wait_group 1;" ::: "memory");   // chunk c landed
        __syncthreads();           // visible to all; consume(c-1) done by all
        if (c + 2 < NC) ISSUE(kbase + (c + 2)*KC, (c + 2) % STAGES);
        asm volatile("cp.async.commit_group;" ::: "memory");
        switch (c % STAGES) {
            case 0: CONSUME(aLd[0], bLd[0]); break;
            case 1: CONSUME(aLd[1], bLd[1]); break;
            default: CONSUME(aLd[2], bLd[2]); break;
        }
    }

    // ---- epilogue ----
    const int g = lane >> 2, t4 = lane & 3;
    const float* bias = (PHASE == 1) ? (b1f + e*DFF + n0) : (b2f + e*D + n0);
    #pragma unroll
    for (int mi = 0; mi < 4; mi++) {
        #pragma unroll
        for (int h = 0; h < 2; h++) {
            int r = wm + 16*mi + g + 8*h;
            int br = r >> 5;
            if (br >= nrows) continue;
            if (PHASE == 1) {
                __half* dst = g_h + ((size_t)(p0*T + r)) * (size_t)DFF + n0;
                #pragma unroll
                for (int ni = 0; ni < 4; ni++) {
                    int col = wn + 8*ni + 2*t4;
                    float v0 = gelu_exact(acc[mi][ni][2*h + 0] + bias[col]);
                    float v1 = gelu_exact(acc[mi][ni][2*h + 1] + bias[col + 1]);
                    *(uint32_t*)(dst + col) = pack_h2(v0, v1);
                }
            } else {
                int n = g_perm[p0 + br];
                float* dst = out + ((size_t)n*T + (r & 31)) * (size_t)D + n0;
                #pragma unroll
                for (int ni = 0; ni < 4; ni++) {
                    int col = wn + 8*ni + 2*t4;
                    float v0 = acc[mi][ni][2*h + 0];
                    float v1 = acc[mi][ni][2*h + 1];
                    if (kp == 0) { v0 += bias[col]; v1 += bias[col + 1]; }
                    atomicAdd(dst + col,     v0);   // 2 contributions onto 0:
                    atomicAdd(dst + col + 1, v1);   // order-invariant
                }
            }
        }
    }
    #undef ISSUE
    #undef CONSUME
}

// ---------------- launch ----------------------------------------------------
extern "C" void kernel_launch(void* const* d_in, const int* in_sizes, int n_in,
                              void* d_out, int out_size) {
    const float* x  = (const float*)d_in[0];
    const float* Wg = (const float*)d_in[2];
    const float* W1 = (const float*)d_in[3];
    const float* b1 = (const float*)d_in[4];
    const float* W2 = (const float*)d_in[5];
    const float* b2 = (const float*)d_in[6];
    float* out = (float*)d_out;

    cudaFuncSetAttribute(ffn_mma<1>, cudaFuncAttributeMaxDynamicSharedMemorySize, SMEM_BYTES);
    cudaFuncSetAttribute(ffn_mma<2>, cudaFuncAttributeMaxDynamicSharedMemorySize, SMEM_BYTES);

    cudaMemsetAsync(out, 0, (size_t)OUT_ELEMS * sizeof(float));
    wcvt_kernel<<<(int)(((size_t)NE*D*DFF/4 + 255)/256), 256>>>(W1, W2);
    half_x_kernel<<<(BZ*T*D/4 + 255)/256, 256>>>(x);
    avg_router_kernel<<<BZ, 256>>>(x, Wg, out, out_size);
    group_kernel<<<1, NROWS>>>();
    ffn_mma<1><<<dim3(MAX_TILES, DFF/NT),  512, SMEM_BYTES>>>(b1, b2, out);
    ffn_mma<2><<<dim3(MAX_TILES, D/NT, 2), 512, SMEM_BYTES>>>(b1, b2, out);
}